// round 2
// baseline (speedup 1.0000x reference)
#include <cuda_runtime.h>
#include <cuda_bf16.h>

#define EPS 1e-7f

// Global scratch (no allocations allowed). Reset by the last block each run,
// so the kernel is deterministic-per-replay and needs no separate zero pass.
__device__ double g_mse_sum = 0.0;
__device__ double g_iou_sum = 0.0;
__device__ unsigned long long g_n_inc = 0ULL;
__device__ unsigned long long g_n_corr = 0ULL;
__device__ unsigned int g_block_count = 0u;

__device__ __forceinline__ float4 ldcs4(const float4* p) {
    return __ldcs(p);
}

struct Acc {
    float mse;
    float iou;
    int inc;
    int corr;
};

__device__ __forceinline__ void process_box(const float4& p, const float4& g, Acc& a) {
    // gt corners
    float x_min_t = g.x - g.z * 0.5f;
    float x_max_t = g.x + g.z * 0.5f;
    float y_min_t = g.y - g.w * 0.5f;
    float y_max_t = g.y + g.w * 0.5f;
    // pred corners, clipped to [0,1]
    float x_min_p = fmaxf(p.x - p.z * 0.5f, 0.0f);
    float x_max_p = fminf(p.x + p.z * 0.5f, 1.0f);
    float y_min_p = fmaxf(p.y - p.w * 0.5f, 0.0f);
    float y_max_p = fminf(p.y + p.w * 0.5f, 1.0f);
    // overlap box
    float o0 = fmaxf(x_min_t, x_min_p);
    float o1 = fmaxf(y_min_t, y_min_p);
    float o2 = fminf(x_max_t, x_max_p);
    float o3 = fminf(y_max_t, y_max_p);

    bool incorrect = (o2 < o0) || (o3 < o1);

    if (incorrect) {
        float dx = p.x - g.x;
        float dy = p.y - g.y;
        float dz = p.z - g.z;
        float dw = p.w - g.w;
        a.mse += dx * dx + dy * dy + dz * dz + dw * dw;
        a.inc += 1;
    } else {
        float area_p = p.z * p.w;
        float area_g = g.z * g.w;
        float inter = (o2 - o0) * (o3 - o1);
        a.iou += inter / (area_p + area_g - inter + EPS);
        a.corr += 1;
    }
}

template <int BLOCK>
__global__ void __launch_bounds__(BLOCK) iou_dots_fused_kernel(
    const float4* __restrict__ pr,
    const float4* __restrict__ gt,
    float* __restrict__ out,
    int n) {
    Acc a = {0.0f, 0.0f, 0, 0};

    const int stride = gridDim.x * BLOCK;
    int i = blockIdx.x * BLOCK + threadIdx.x;

    // Unrolled-by-4 main loop: 8 independent 128-bit loads in flight.
    for (; i + 3 * stride < n; i += 4 * stride) {
        float4 p0 = ldcs4(pr + i);
        float4 p1 = ldcs4(pr + i + stride);
        float4 p2 = ldcs4(pr + i + 2 * stride);
        float4 p3 = ldcs4(pr + i + 3 * stride);
        float4 g0 = ldcs4(gt + i);
        float4 g1 = ldcs4(gt + i + stride);
        float4 g2 = ldcs4(gt + i + 2 * stride);
        float4 g3 = ldcs4(gt + i + 3 * stride);
        process_box(p0, g0, a);
        process_box(p1, g1, a);
        process_box(p2, g2, a);
        process_box(p3, g3, a);
    }
    for (; i < n; i += stride) {
        float4 p = ldcs4(pr + i);
        float4 g = ldcs4(gt + i);
        process_box(p, g, a);
    }

    // Warp reduce
    #pragma unroll
    for (int off = 16; off > 0; off >>= 1) {
        a.mse += __shfl_down_sync(0xFFFFFFFFu, a.mse, off);
        a.iou += __shfl_down_sync(0xFFFFFFFFu, a.iou, off);
        a.inc += __shfl_down_sync(0xFFFFFFFFu, a.inc, off);
        a.corr += __shfl_down_sync(0xFFFFFFFFu, a.corr, off);
    }

    __shared__ double s_mse[BLOCK / 32];
    __shared__ double s_iou[BLOCK / 32];
    __shared__ int s_inc[BLOCK / 32];
    __shared__ int s_corr[BLOCK / 32];
    __shared__ bool s_is_last;

    int lane = threadIdx.x & 31;
    int wid = threadIdx.x >> 5;
    if (lane == 0) {
        s_mse[wid] = (double)a.mse;
        s_iou[wid] = (double)a.iou;
        s_inc[wid] = a.inc;
        s_corr[wid] = a.corr;
    }
    __syncthreads();

    if (wid == 0) {
        constexpr int NW = BLOCK / 32;
        double m = (lane < NW) ? s_mse[lane] : 0.0;
        double u = (lane < NW) ? s_iou[lane] : 0.0;
        int ni = (lane < NW) ? s_inc[lane] : 0;
        int nc = (lane < NW) ? s_corr[lane] : 0;
        #pragma unroll
        for (int off = 16; off > 0; off >>= 1) {
            m += __shfl_down_sync(0xFFFFFFFFu, m, off);
            u += __shfl_down_sync(0xFFFFFFFFu, u, off);
            ni += __shfl_down_sync(0xFFFFFFFFu, ni, off);
            nc += __shfl_down_sync(0xFFFFFFFFu, nc, off);
        }
        if (lane == 0) {
            atomicAdd(&g_mse_sum, m);
            atomicAdd(&g_iou_sum, u);
            atomicAdd(&g_n_inc, (unsigned long long)ni);
            atomicAdd(&g_n_corr, (unsigned long long)nc);
            __threadfence();
            unsigned int done = atomicAdd(&g_block_count, 1u);
            s_is_last = (done == gridDim.x - 1u);
        }
    }
    __syncthreads();

    // Last block finalizes and resets scratch for the next graph replay.
    if (s_is_last && threadIdx.x == 0) {
        double mse_sum = g_mse_sum;
        double iou_sum = g_iou_sum;
        unsigned long long n_inc = g_n_inc;
        unsigned long long n_corr = g_n_corr;

        double denom_mse = (double)((n_inc > 0ULL) ? n_inc * 4ULL : 1ULL);
        double mse_mean = mse_sum / denom_mse;
        double denom_iou = (double)((n_corr > 0ULL) ? n_corr : 1ULL);
        double iou_mean = iou_sum / denom_iou;

        double res;
        if (n_corr > 0ULL) {
            res = iou_mean + ((n_inc > 0ULL) ? -mse_mean : 0.0);
        } else {
            res = -mse_mean;
        }
        out[0] = (float)res;

        // Reset for next replay.
        g_mse_sum = 0.0;
        g_iou_sum = 0.0;
        g_n_inc = 0ULL;
        g_n_corr = 0ULL;
        __threadfence();
        g_block_count = 0u;
    }
}

extern "C" void kernel_launch(void* const* d_in, const int* in_sizes, int n_in,
                              void* d_out, int out_size) {
    const float4* pr = (const float4*)d_in[0];
    const float4* gt = (const float4*)d_in[1];
    float* out = (float*)d_out;
    int n = in_sizes[0] / 4;  // element count -> box count

    constexpr int BLOCK = 256;
    int blocks = 148 * 8;  // 1184 blocks, grid-stride, occ=8

    iou_dots_fused_kernel<BLOCK><<<blocks, BLOCK>>>(pr, gt, out, n);
}

// round 5
// speedup vs baseline: 1.0888x; 1.0888x over previous
#include <cuda_runtime.h>
#include <cuda_bf16.h>

#define EPS 1e-7f

// Global scratch (no allocations allowed). Reset by the last block each run,
// so the kernel is deterministic-per-replay and needs no separate zero pass.
__device__ double g_mse_sum = 0.0;
__device__ double g_iou_sum = 0.0;
__device__ unsigned long long g_n_inc = 0ULL;
__device__ unsigned long long g_n_corr = 0ULL;
__device__ unsigned int g_block_count = 0u;

__device__ __forceinline__ float4 ldcs4(const float4* p) {
    return __ldcs(p);
}

struct Acc {
    float mse;
    float iou;
    int inc;
    int corr;
};

__device__ __forceinline__ void process_box(const float4& p, const float4& g, Acc& a) {
    // gt corners
    float x_min_t = g.x - g.z * 0.5f;
    float x_max_t = g.x + g.z * 0.5f;
    float y_min_t = g.y - g.w * 0.5f;
    float y_max_t = g.y + g.w * 0.5f;
    // pred corners, clipped to [0,1]
    float x_min_p = fmaxf(p.x - p.z * 0.5f, 0.0f);
    float x_max_p = fminf(p.x + p.z * 0.5f, 1.0f);
    float y_min_p = fmaxf(p.y - p.w * 0.5f, 0.0f);
    float y_max_p = fminf(p.y + p.w * 0.5f, 1.0f);
    // overlap box
    float o0 = fmaxf(x_min_t, x_min_p);
    float o1 = fmaxf(y_min_t, y_min_p);
    float o2 = fminf(x_max_t, x_max_p);
    float o3 = fminf(y_max_t, y_max_p);

    bool incorrect = (o2 < o0) || (o3 < o1);

    if (incorrect) {
        float dx = p.x - g.x;
        float dy = p.y - g.y;
        float dz = p.z - g.z;
        float dw = p.w - g.w;
        a.mse += dx * dx + dy * dy + dz * dz + dw * dw;
        a.inc += 1;
    } else {
        float area_p = p.z * p.w;
        float area_g = g.z * g.w;
        float inter = (o2 - o0) * (o3 - o1);
        a.iou += inter / (area_p + area_g - inter + EPS);
        a.corr += 1;
    }
}

template <int BLOCK>
__global__ void __launch_bounds__(BLOCK, 6) iou_dots_fused_kernel(
    const float4* __restrict__ pr,
    const float4* __restrict__ gt,
    float* __restrict__ out,
    int n) {
    Acc a = {0.0f, 0.0f, 0, 0};

    const int stride = gridDim.x * BLOCK;
    int i = blockIdx.x * BLOCK + threadIdx.x;

    // Unrolled-by-2 main loop: 4 independent 128-bit loads in flight,
    // register footprint capped (<=42 regs) via launch_bounds for occ=6.
    for (; i + stride < n; i += 2 * stride) {
        float4 p0 = ldcs4(pr + i);
        float4 p1 = ldcs4(pr + i + stride);
        float4 g0 = ldcs4(gt + i);
        float4 g1 = ldcs4(gt + i + stride);
        process_box(p0, g0, a);
        process_box(p1, g1, a);
    }
    if (i < n) {
        float4 p = ldcs4(pr + i);
        float4 g = ldcs4(gt + i);
        process_box(p, g, a);
    }

    // Warp reduce
    #pragma unroll
    for (int off = 16; off > 0; off >>= 1) {
        a.mse += __shfl_down_sync(0xFFFFFFFFu, a.mse, off);
        a.iou += __shfl_down_sync(0xFFFFFFFFu, a.iou, off);
        a.inc += __shfl_down_sync(0xFFFFFFFFu, a.inc, off);
        a.corr += __shfl_down_sync(0xFFFFFFFFu, a.corr, off);
    }

    __shared__ double s_mse[BLOCK / 32];
    __shared__ double s_iou[BLOCK / 32];
    __shared__ int s_inc[BLOCK / 32];
    __shared__ int s_corr[BLOCK / 32];
    __shared__ bool s_is_last;

    int lane = threadIdx.x & 31;
    int wid = threadIdx.x >> 5;
    if (lane == 0) {
        s_mse[wid] = (double)a.mse;
        s_iou[wid] = (double)a.iou;
        s_inc[wid] = a.inc;
        s_corr[wid] = a.corr;
    }
    __syncthreads();

    if (wid == 0) {
        constexpr int NW = BLOCK / 32;
        double m = (lane < NW) ? s_mse[lane] : 0.0;
        double u = (lane < NW) ? s_iou[lane] : 0.0;
        int ni = (lane < NW) ? s_inc[lane] : 0;
        int nc = (lane < NW) ? s_corr[lane] : 0;
        #pragma unroll
        for (int off = 16; off > 0; off >>= 1) {
            m += __shfl_down_sync(0xFFFFFFFFu, m, off);
            u += __shfl_down_sync(0xFFFFFFFFu, u, off);
            ni += __shfl_down_sync(0xFFFFFFFFu, ni, off);
            nc += __shfl_down_sync(0xFFFFFFFFu, nc, off);
        }
        if (lane == 0) {
            atomicAdd(&g_mse_sum, m);
            atomicAdd(&g_iou_sum, u);
            atomicAdd(&g_n_inc, (unsigned long long)ni);
            atomicAdd(&g_n_corr, (unsigned long long)nc);
            __threadfence();
            unsigned int done = atomicAdd(&g_block_count, 1u);
            s_is_last = (done == gridDim.x - 1u);
        }
    }
    __syncthreads();

    // Last block finalizes and resets scratch for the next graph replay.
    if (s_is_last && threadIdx.x == 0) {
        double mse_sum = g_mse_sum;
        double iou_sum = g_iou_sum;
        unsigned long long n_inc = g_n_inc;
        unsigned long long n_corr = g_n_corr;

        double denom_mse = (double)((n_inc > 0ULL) ? n_inc * 4ULL : 1ULL);
        double mse_mean = mse_sum / denom_mse;
        double denom_iou = (double)((n_corr > 0ULL) ? n_corr : 1ULL);
        double iou_mean = iou_sum / denom_iou;

        double res;
        if (n_corr > 0ULL) {
            res = iou_mean + ((n_inc > 0ULL) ? -mse_mean : 0.0);
        } else {
            res = -mse_mean;
        }
        out[0] = (float)res;

        // Reset for next replay.
        g_mse_sum = 0.0;
        g_iou_sum = 0.0;
        g_n_inc = 0ULL;
        g_n_corr = 0ULL;
        __threadfence();
        g_block_count = 0u;
    }
}

extern "C" void kernel_launch(void* const* d_in, const int* in_sizes, int n_in,
                              void* d_out, int out_size) {
    const float4* pr = (const float4*)d_in[0];
    const float4* gt = (const float4*)d_in[1];
    float* out = (float*)d_out;
    int n = in_sizes[0] / 4;  // element count -> box count

    constexpr int BLOCK = 256;
    int blocks = 148 * 6;  // 888 blocks = exactly one wave at 6 blocks/SM

    iou_dots_fused_kernel<BLOCK><<<blocks, BLOCK>>>(pr, gt, out, n);
}